// round 16
// baseline (speedup 1.0000x reference)
#include <cuda_runtime.h>
#include <cuda_bf16.h>
#include <cuda_fp16.h>
#include <math.h>
#include <stdint.h>

#define T_TOK 2048
#define DIM   1024
#define NEXP  8
#define HID   2048

#define BM 128
#define BN 128
#define BK 64              // K elements per chunk (128B payload per row)
#define ROWB 144           // padded row stride bytes (9 x 16B) -> conflict-free ldmatrix
#define PB (128 * ROWB)    // plane bytes = 18432
#define STAGES 3
#define PLANES 2           // A, B
#define GRIDP 304          // persistent grid: 2 CTAs/SM x 152 SMs

#define TD (T_TOK * DIM)

// ---------------- scratch (device globals; no allocation allowed) ----------
__device__ int   g_cnt[NEXP];
__device__ int   g_tok[NEXP * T_TOK];    // t | (slot << 12)
__device__ float g_wgt[NEXP * T_TOK];
__device__ __align__(256) __half g_x[T_TOK * DIM];
__device__ __align__(256) __half g_wu[NEXP * HID * DIM];
__device__ __align__(256) __half g_wd[NEXP * DIM * HID];
__device__ __align__(256) __half g_h[(size_t)NEXP * T_TOK * HID];

// ---------------- helpers ---------------------------------------------------
__device__ __forceinline__ uint32_t smem_u32(const void* p) {
    return (uint32_t)__cvta_generic_to_shared(p);
}
__device__ __forceinline__ void cpa16(uint32_t dst, const void* src) {
    asm volatile("cp.async.cg.shared.global [%0], [%1], 16;\n"
                 :: "r"(dst), "l"(src) : "memory");
}
__device__ __forceinline__ void ldmx4(uint32_t& r0, uint32_t& r1, uint32_t& r2,
                                      uint32_t& r3, uint32_t addr) {
    asm volatile("ldmatrix.sync.aligned.m8n8.x4.shared.b16 {%0,%1,%2,%3}, [%4];\n"
                 : "=r"(r0), "=r"(r1), "=r"(r2), "=r"(r3) : "r"(addr));
}
__device__ __forceinline__ void mma_fp16(float* d, const uint32_t* a, const uint32_t* b) {
    asm volatile("mma.sync.aligned.m16n8k16.row.col.f32.f16.f16.f32 "
                 "{%0,%1,%2,%3}, {%4,%5,%6,%7}, {%8,%9}, {%0,%1,%2,%3};\n"
                 : "+f"(d[0]), "+f"(d[1]), "+f"(d[2]), "+f"(d[3])
                 : "r"(a[0]), "r"(a[1]), "r"(a[2]), "r"(a[3]), "r"(b[0]), "r"(b[1]));
}
__device__ __forceinline__ void cvt8_store(const float* __restrict__ src,
                                           __half* __restrict__ dst, int off) {
    float4 v0 = *(const float4*)(src + off);
    float4 v1 = *(const float4*)(src + off + 4);
    __half2 a = __floats2half2_rn(v0.x, v0.y);
    __half2 b = __floats2half2_rn(v0.z, v0.w);
    __half2 c = __floats2half2_rn(v1.x, v1.y);
    __half2 d = __floats2half2_rn(v1.z, v1.w);
    *(uint4*)(dst + off) = make_uint4(*(uint32_t*)&a, *(uint32_t*)&b,
                                      *(uint32_t*)&c, *(uint32_t*)&d);
}

// ---------------- init -------------------------------------------------------
__global__ void init_counts_kernel() {
    if (threadIdx.x < NEXP) g_cnt[threadIdx.x] = 0;
}

// ---------------- fused router + prepass (x, w_up only) ---------------------
// Blocks [0, RB): sigmoid top-2 router, 8 tokens per block (1 warp/token).
// Blocks [RB, ...): fp32 -> fp16 conversion of x and w_up (8 floats/thread).
#define RB (T_TOK / 8)     // 256 router blocks

__global__ void fused_route_prepass_kernel(const float* __restrict__ x,
                                           const float* __restrict__ gate_w,
                                           const float* __restrict__ bias,
                                           const float* __restrict__ w_up) {
    if (blockIdx.x < RB) {
        int warp = threadIdx.x >> 5;
        int lane = threadIdx.x & 31;
        int t = blockIdx.x * 8 + warp;

        float s[NEXP];
#pragma unroll
        for (int e = 0; e < NEXP; e++) s[e] = 0.f;
        const float* xr = x + (size_t)t * DIM;
        for (int d = lane; d < DIM; d += 32) {
            float xv = xr[d];
#pragma unroll
            for (int e = 0; e < NEXP; e++) s[e] += xv * gate_w[e * DIM + d];
        }
#pragma unroll
        for (int e = 0; e < NEXP; e++)
#pragma unroll
            for (int o = 16; o > 0; o >>= 1)
                s[e] += __shfl_xor_sync(0xffffffffu, s[e], o);

        if (lane == 0) {
            float sig[NEXP], b[NEXP];
#pragma unroll
            for (int e = 0; e < NEXP; e++) {
                sig[e] = 1.f / (1.f + expf(-s[e]));
                b[e] = sig[e] + bias[e];
            }
            int e0 = 0;
            for (int e = 1; e < NEXP; e++) if (b[e] > b[e0]) e0 = e;
            int e1 = -1;
            for (int e = 0; e < NEXP; e++) {
                if (e == e0) continue;
                if (e1 < 0 || b[e] > b[e1]) e1 = e;
            }
            int p0 = atomicAdd(&g_cnt[e0], 1);
            g_tok[e0 * T_TOK + p0] = t;                 // slot 0
            g_wgt[e0 * T_TOK + p0] = sig[e0];
            int p1 = atomicAdd(&g_cnt[e1], 1);
            g_tok[e1 * T_TOK + p1] = t | (1 << 12);     // slot 1
            g_wgt[e1 * T_TOK + p1] = sig[e1];
        }
        return;
    }

    // conversion region: x then w_up, 8 floats per thread
    constexpr int NX  = T_TOK * DIM;
    constexpr int NWU = NEXP * HID * DIM;
    int i8 = ((blockIdx.x - RB) * blockDim.x + threadIdx.x) * 8;
    if (i8 >= NX + NWU) return;
    if (i8 < NX) cvt8_store(x, g_x, i8);
    else         cvt8_store(w_up, g_wu, i8 - NX);
}

// ---------------- persistent grouped GEMM -----------------------------------
// MODE 0 (up):   z = gather(x) @ wu^T; epilogue h = (s*relu(z))^2 -> fp16;
//                then grid-strided w_down fp32->fp16 conversion in the tail
//                (hidden in the persistent-wave straggler shadow).
// MODE 1 (down): A = h, B = wd; epilogue atomicAdd into out (2 adds/elem).
template <int MODE>
__global__ __launch_bounds__(256, 2)
void moe_gemm_kernel(float* __restrict__ outp, const float* __restrict__ w_down) {
    constexpr int KT  = (MODE == 0) ? DIM : HID;
    constexpr int NC  = KT / BK;              // up: 16, down: 32
    constexpr int NXT = (MODE == 0) ? (HID / BN) : (DIM / BN);

    extern __shared__ __align__(1024) char smem_dyn[];
    __shared__ int   row_tok_s[BM];
    __shared__ float row_w_s[BM];
    const uint32_t sbase = smem_u32(smem_dyn);

    const int tid = threadIdx.x, warp = tid >> 5, lane = tid & 31;
    const int wm = warp & 3, wn = warp >> 2;
    const int rm = wm * 32, cn = wn * 64;

    // local tile-prefix over live tiles
    int off[NEXP + 1];
    {
        int acc_t = 0;
#pragma unroll
        for (int e = 0; e < NEXP; e++) {
            off[e] = acc_t;
            acc_t += ((g_cnt[e] + BM - 1) / BM) * NXT;
        }
        off[NEXP] = acc_t;
    }
    const int total = off[NEXP];

    for (int tw = blockIdx.x; tw < total; tw += gridDim.x) {
        int e = 0;
        while (tw >= off[e + 1]) e++;
        const int local = tw - off[e];
        const int i0 = (local / NXT) * BM;
        const int j0 = (local % NXT) * BN;
        const int cnt = g_cnt[e];

        __syncthreads();   // previous tile's epilogue done reading row_* arrays
        for (int i = tid; i < BM; i += 256) {
            int gi = i0 + i; int tk = 0; float w = 0.f;
            if (gi < cnt) { tk = g_tok[e * T_TOK + gi]; w = g_wgt[e * T_TOK + gi]; }
            row_tok_s[i] = tk; row_w_s[i] = w;
        }
        __syncthreads();

        float acc[2][8][4];
#pragma unroll
        for (int a = 0; a < 2; a++)
#pragma unroll
            for (int b = 0; b < 8; b++)
#pragma unroll
                for (int c = 0; c < 4; c++) acc[a][b][c] = 0.f;

        auto load_chunk = [&](int c) {
            const int k0 = c * BK;
            const uint32_t st = sbase + (uint32_t)(c % STAGES) * PLANES * PB;
#pragma unroll
            for (int p = 0; p < PLANES; p++) {
#pragma unroll
                for (int q = 0; q < 4; q++) {
                    int id  = tid + q * 256;          // 0..1023
                    int r   = id >> 3;                // row 0..127
                    int c16 = id & 7;                 // 16B chunk in 128B row payload
                    const void* src;
                    if (MODE == 0) {
                        if (p == 0)
                            src = g_x + (size_t)(row_tok_s[r] & 0xFFF) * DIM + k0 + c16 * 8;
                        else
                            src = g_wu + ((size_t)e * HID + j0 + r) * DIM + k0 + c16 * 8;
                    } else {
                        if (p == 0)
                            src = g_h + ((size_t)e * T_TOK + i0 + r) * HID + k0 + c16 * 8;
                        else
                            src = g_wd + ((size_t)e * DIM + j0 + r) * HID + k0 + c16 * 8;
                    }
                    cpa16(st + (uint32_t)p * PB + (uint32_t)(r * ROWB + c16 * 16), src);
                }
            }
            asm volatile("cp.async.commit_group;\n" ::: "memory");
        };

        // prologue: fill STAGES-1 stages
#pragma unroll
        for (int c = 0; c < STAGES - 1; c++) load_chunk(c);

        for (int c = 0; c < NC; c++) {
            // Steady state: wait_group(STAGES-2) retires exactly chunk c.
            // Tail (no further commits): drain fully.
            if (c + STAGES - 1 < NC) {
                asm volatile("cp.async.wait_group %0;\n" :: "n"(STAGES - 2) : "memory");
            } else {
                asm volatile("cp.async.wait_group 0;\n" ::: "memory");
            }
            __syncthreads();   // chunk c visible; all warps done with chunk c-1
            if (c + STAGES - 1 < NC) load_chunk(c + STAGES - 1);

            const uint32_t st = sbase + (uint32_t)(c % STAGES) * PLANES * PB;
#pragma unroll
            for (int kk = 0; kk < BK; kk += 16) {
                uint32_t af[2][4];
#pragma unroll
                for (int mi = 0; mi < 2; mi++) {
                    uint32_t addr = st +
                        (uint32_t)((rm + mi * 16 + (lane & 15)) * ROWB +
                                   (kk + (lane >> 4) * 8) * 2);
                    ldmx4(af[mi][0], af[mi][1], af[mi][2], af[mi][3], addr);
                }
                uint32_t bf[8][2];
#pragma unroll
                for (int nb = 0; nb < 4; nb++) {
                    int nrow = cn + nb * 16 + (lane & 7) + (((lane >> 4) & 1) << 3);
                    int kcol = kk + ((lane & 8) ? 8 : 0);
                    uint32_t addr = st + PB + (uint32_t)(nrow * ROWB + kcol * 2);
                    uint32_t r0, r1, r2, r3;
                    ldmx4(r0, r1, r2, r3, addr);
                    bf[nb * 2][0] = r0;      bf[nb * 2][1] = r1;
                    bf[nb * 2 + 1][0] = r2;  bf[nb * 2 + 1][1] = r3;
                }
#pragma unroll
                for (int mi = 0; mi < 2; mi++)
#pragma unroll
                    for (int ni = 0; ni < 8; ni++)
                        mma_fp16(acc[mi][ni], af[mi], bf[ni]);
            }
        }

        // ---------------- epilogue ----------------
        const int tg = lane >> 2;          // 0..7
        const int tc = (lane & 3) << 1;    // 0,2,4,6
#pragma unroll
        for (int mi = 0; mi < 2; mi++)
#pragma unroll
            for (int ni = 0; ni < 8; ni++)
#pragma unroll
                for (int rh = 0; rh < 2; rh++) {
                    int r  = rm + mi * 16 + tg + rh * 8;
                    int c0 = cn + ni * 8 + tc;
                    int gi = i0 + r;
                    if (gi < cnt) {
                        float v0 = acc[mi][ni][2 * rh];
                        float v1 = acc[mi][ni][2 * rh + 1];
                        if (MODE == 0) {
                            float sw = row_w_s[r];
                            float f0 = sw * fmaxf(v0, 0.f); f0 *= f0;
                            float f1 = sw * fmaxf(v1, 0.f); f1 *= f1;
                            __half2 h2 = __floats2half2_rn(f0, f1);
                            *(__half2*)(g_h + ((size_t)e * T_TOK + gi) * HID + j0 + c0) = h2;
                        } else {
                            int t = row_tok_s[r] & 0xFFF;
                            // exactly 2 commutative fp32 adds per element -> deterministic
                            atomicAdd(outp + (size_t)t * DIM + j0 + c0, v0);
                            atomicAdd(outp + (size_t)t * DIM + j0 + c0 + 1, v1);
                        }
                    }
                }
    }

    // ---- up-GEMM tail: convert w_down fp32 -> fp16 (overlaps stragglers) ----
    if (MODE == 0) {
        constexpr int NWD = NEXP * DIM * HID;
        for (int i8 = (blockIdx.x * 256 + tid) * 8; i8 < NWD;
             i8 += gridDim.x * 256 * 8)
            cvt8_store(w_down, g_wd, i8);
    }
}

// ---------------- launch -----------------------------------------------------
extern "C" void kernel_launch(void* const* d_in, const int* in_sizes, int n_in,
                              void* d_out, int out_size) {
    const float* x      = (const float*)d_in[0];
    const float* gate_w = (const float*)d_in[1];
    const float* w_up   = (const float*)d_in[2];
    const float* w_down = (const float*)d_in[3];
    const float* bias   = (const float*)d_in[4];
    float* out = (float*)d_out;

    constexpr int SMEM_GEMM = STAGES * PLANES * PB;   // 110592
    cudaFuncSetAttribute(moe_gemm_kernel<0>,
                         cudaFuncAttributeMaxDynamicSharedMemorySize, SMEM_GEMM);
    cudaFuncSetAttribute(moe_gemm_kernel<1>,
                         cudaFuncAttributeMaxDynamicSharedMemorySize, SMEM_GEMM);

    init_counts_kernel<<<1, 32>>>();
    cudaMemsetAsync(d_out, 0, (size_t)out_size * sizeof(float));

    {
        constexpr int NXWU = T_TOK * DIM + NEXP * HID * DIM;
        constexpr int CONV_BLOCKS = (NXWU / 8 + 255) / 256;
        fused_route_prepass_kernel<<<RB + CONV_BLOCKS, 256>>>(x, gate_w, bias, w_up);
    }

    moe_gemm_kernel<0><<<GRIDP, 256, SMEM_GEMM>>>(nullptr, w_down);
    moe_gemm_kernel<1><<<GRIDP, 256, SMEM_GEMM>>>(out, nullptr);
    (void)in_sizes; (void)n_in;
}

// round 17
// speedup vs baseline: 1.0798x; 1.0798x over previous
#include <cuda_runtime.h>
#include <cuda_bf16.h>
#include <cuda_fp16.h>
#include <math.h>
#include <stdint.h>

#define T_TOK 2048
#define DIM   1024
#define NEXP  8
#define HID   2048

#define BM 128
#define BN 128
#define BK 64              // K elements per chunk (128B payload per row)
#define ROWB 144           // padded row stride bytes (9 x 16B) -> conflict-free ldmatrix
#define PB (128 * ROWB)    // plane bytes = 18432
#define STAGES 3
#define PLANES 2           // A, B
#define GRIDP 304          // persistent grid: 2 CTAs/SM x 152 SMs

// ---------------- scratch (device globals; no allocation allowed) ----------
__device__ int   g_cnt[NEXP];
__device__ int   g_done[NEXP];           // completed up tiles per expert
__device__ int   g_tok[NEXP * T_TOK];    // t | (slot << 12)
__device__ float g_wgt[NEXP * T_TOK];
__device__ __align__(256) __half g_x[T_TOK * DIM];
__device__ __align__(256) __half g_wu[NEXP * HID * DIM];
__device__ __align__(256) __half g_wd[NEXP * DIM * HID];
__device__ __align__(256) __half g_h[(size_t)NEXP * T_TOK * HID];

// ---------------- helpers ---------------------------------------------------
__device__ __forceinline__ uint32_t smem_u32(const void* p) {
    return (uint32_t)__cvta_generic_to_shared(p);
}
__device__ __forceinline__ void cpa16(uint32_t dst, const void* src) {
    asm volatile("cp.async.cg.shared.global [%0], [%1], 16;\n"
                 :: "r"(dst), "l"(src) : "memory");
}
__device__ __forceinline__ void ldmx4(uint32_t& r0, uint32_t& r1, uint32_t& r2,
                                      uint32_t& r3, uint32_t addr) {
    asm volatile("ldmatrix.sync.aligned.m8n8.x4.shared.b16 {%0,%1,%2,%3}, [%4];\n"
                 : "=r"(r0), "=r"(r1), "=r"(r2), "=r"(r3) : "r"(addr));
}
__device__ __forceinline__ void mma_fp16(float* d, const uint32_t* a, const uint32_t* b) {
    asm volatile("mma.sync.aligned.m16n8k16.row.col.f32.f16.f16.f32 "
                 "{%0,%1,%2,%3}, {%4,%5,%6,%7}, {%8,%9}, {%0,%1,%2,%3};\n"
                 : "+f"(d[0]), "+f"(d[1]), "+f"(d[2]), "+f"(d[3])
                 : "r"(a[0]), "r"(a[1]), "r"(a[2]), "r"(a[3]), "r"(b[0]), "r"(b[1]));
}
__device__ __forceinline__ void cvt8_store(const float* __restrict__ src,
                                           __half* __restrict__ dst, int off) {
    float4 v0 = *(const float4*)(src + off);
    float4 v1 = *(const float4*)(src + off + 4);
    __half2 a = __floats2half2_rn(v0.x, v0.y);
    __half2 b = __floats2half2_rn(v0.z, v0.w);
    __half2 c = __floats2half2_rn(v1.x, v1.y);
    __half2 d = __floats2half2_rn(v1.z, v1.w);
    *(uint4*)(dst + off) = make_uint4(*(uint32_t*)&a, *(uint32_t*)&b,
                                      *(uint32_t*)&c, *(uint32_t*)&d);
}

// ---------------- init -------------------------------------------------------
__global__ void init_counts_kernel() {
    if (threadIdx.x < NEXP) { g_cnt[threadIdx.x] = 0; g_done[threadIdx.x] = 0; }
}

// ---------------- fused router + prepass (x, w_up, w_down) ------------------
// Blocks [0, RB): sigmoid top-2 router, 8 tokens per block (1 warp/token).
// Blocks [RB, ...): fp32 -> fp16 conversion (8 floats/thread).
#define RB (T_TOK / 8)     // 256 router blocks

__global__ void fused_route_prepass_kernel(const float* __restrict__ x,
                                           const float* __restrict__ gate_w,
                                           const float* __restrict__ bias,
                                           const float* __restrict__ w_up,
                                           const float* __restrict__ w_down) {
    if (blockIdx.x < RB) {
        int warp = threadIdx.x >> 5;
        int lane = threadIdx.x & 31;
        int t = blockIdx.x * 8 + warp;

        float s[NEXP];
#pragma unroll
        for (int e = 0; e < NEXP; e++) s[e] = 0.f;
        const float* xr = x + (size_t)t * DIM;
        for (int d = lane; d < DIM; d += 32) {
            float xv = xr[d];
#pragma unroll
            for (int e = 0; e < NEXP; e++) s[e] += xv * gate_w[e * DIM + d];
        }
#pragma unroll
        for (int e = 0; e < NEXP; e++)
#pragma unroll
            for (int o = 16; o > 0; o >>= 1)
                s[e] += __shfl_xor_sync(0xffffffffu, s[e], o);

        if (lane == 0) {
            float sig[NEXP], b[NEXP];
#pragma unroll
            for (int e = 0; e < NEXP; e++) {
                sig[e] = 1.f / (1.f + expf(-s[e]));
                b[e] = sig[e] + bias[e];
            }
            int e0 = 0;
            for (int e = 1; e < NEXP; e++) if (b[e] > b[e0]) e0 = e;
            int e1 = -1;
            for (int e = 0; e < NEXP; e++) {
                if (e == e0) continue;
                if (e1 < 0 || b[e] > b[e1]) e1 = e;
            }
            int p0 = atomicAdd(&g_cnt[e0], 1);
            g_tok[e0 * T_TOK + p0] = t;                 // slot 0
            g_wgt[e0 * T_TOK + p0] = sig[e0];
            int p1 = atomicAdd(&g_cnt[e1], 1);
            g_tok[e1 * T_TOK + p1] = t | (1 << 12);     // slot 1
            g_wgt[e1 * T_TOK + p1] = sig[e1];
        }
        return;
    }

    constexpr int NX  = T_TOK * DIM;
    constexpr int NWU = NEXP * HID * DIM;
    constexpr int NWD = NEXP * DIM * HID;
    int i8 = ((blockIdx.x - RB) * blockDim.x + threadIdx.x) * 8;
    if (i8 >= NX + NWU + NWD) return;
    if (i8 < NX)            cvt8_store(x, g_x, i8);
    else if (i8 < NX + NWU) cvt8_store(w_up, g_wu, i8 - NX);
    else                    cvt8_store(w_down, g_wd, i8 - NX - NWU);
}

// ---------------- fused persistent grouped GEMM (up + down) -----------------
// Work list: [0, upTotal) = up tiles; [upTotal, total) = down tiles.
// Up tile:   z = gather(x) @ wu^T; h = (s*relu(z))^2 -> fp16; then
//            fence + per-expert completion counter (release).
// Down tile: spin until expert's up tiles complete (acquire), then
//            A = h, B = wd; epilogue atomicAdd into out (2 adds/elem).
__global__ __launch_bounds__(256, 2)
void moe_fused_gemm_kernel(float* __restrict__ outp) {
    extern __shared__ __align__(1024) char smem_dyn[];
    __shared__ int   row_off_s[BM];   // A-plane row offset (elements)
    __shared__ int   row_tok_s[BM];
    __shared__ float row_w_s[BM];
    const uint32_t sbase = smem_u32(smem_dyn);

    const int tid = threadIdx.x, warp = tid >> 5, lane = tid & 31;
    const int wm = warp & 3, wn = warp >> 2;
    const int rm = wm * 32, cn = wn * 64;

    // tile-prefix over live tiles: up then down
    int offU[NEXP + 1], offD[NEXP + 1];
    {
        int au = 0, ad = 0;
#pragma unroll
        for (int e = 0; e < NEXP; e++) {
            offU[e] = au; offD[e] = ad;
            int mt = (g_cnt[e] + BM - 1) / BM;
            au += mt * (HID / BN);
            ad += mt * (DIM / BN);
        }
        offU[NEXP] = au; offD[NEXP] = ad;
    }
    const int upTotal = offU[NEXP];
    const int total   = upTotal + offD[NEXP];

    for (int tw = blockIdx.x; tw < total; tw += gridDim.x) {
        const bool isUp = tw < upTotal;
        const int  twl  = isUp ? tw : tw - upTotal;
        const int* off  = isUp ? offU : offD;
        const int  NXT  = isUp ? (HID / BN) : (DIM / BN);
        int e = 0;
        while (twl >= off[e + 1]) e++;
        const int local = twl - off[e];
        const int i0 = (local / NXT) * BM;
        const int j0 = (local % NXT) * BN;
        const int cnt = g_cnt[e];
        const int KT = isUp ? DIM : HID;
        const int NC = KT / BK;

        // down tiles: wait for this expert's up tiles (producers are earlier
        // in the static work list; all CTAs are resident -> no deadlock)
        if (!isUp) {
            const int need = ((cnt + BM - 1) / BM) * (HID / BN);
            if (tid == 0) {
                while (atomicAdd(&g_done[e], 0) < need) __nanosleep(64);
            }
            __syncthreads();
        }

        __syncthreads();   // previous tile's epilogue done with row_* arrays
        for (int i = tid; i < BM; i += 256) {
            int gi = i0 + i; int tk = 0; float w = 0.f;
            if (gi < cnt) { tk = g_tok[e * T_TOK + gi]; w = g_wgt[e * T_TOK + gi]; }
            row_tok_s[i] = tk; row_w_s[i] = w;
            row_off_s[i] = isUp ? (tk & 0xFFF) * DIM
                                : (e * T_TOK + i0 + i) * HID;
        }
        __syncthreads();

        const __half* Abase = isUp ? g_x : g_h;
        const __half* Bbase = isUp ? (g_wu + (size_t)e * HID * DIM)
                                   : (g_wd + (size_t)e * DIM * HID);

        float acc[2][8][4];
#pragma unroll
        for (int a = 0; a < 2; a++)
#pragma unroll
            for (int b = 0; b < 8; b++)
#pragma unroll
                for (int c = 0; c < 4; c++) acc[a][b][c] = 0.f;

        auto load_chunk = [&](int c) {
            const int k0 = c * BK;
            const uint32_t st = sbase + (uint32_t)(c % STAGES) * PLANES * PB;
#pragma unroll
            for (int q = 0; q < 4; q++) {
                int id  = tid + q * 256;          // 0..1023
                int r   = id >> 3;                // row 0..127
                int c16 = id & 7;                 // 16B chunk in 128B row payload
                uint32_t soff = (uint32_t)(r * ROWB + c16 * 16);
                cpa16(st + soff, Abase + (size_t)row_off_s[r] + k0 + c16 * 8);
                cpa16(st + PB + soff,
                      Bbase + (size_t)(j0 + r) * KT + k0 + c16 * 8);
            }
            asm volatile("cp.async.commit_group;\n" ::: "memory");
        };

        // prologue: fill STAGES-1 stages
#pragma unroll
        for (int c = 0; c < STAGES - 1; c++) load_chunk(c);

        for (int c = 0; c < NC; c++) {
            // Steady state: wait_group(STAGES-2) retires exactly chunk c.
            // Tail (no further commits): drain fully.
            if (c + STAGES - 1 < NC) {
                asm volatile("cp.async.wait_group %0;\n" :: "n"(STAGES - 2) : "memory");
            } else {
                asm volatile("cp.async.wait_group 0;\n" ::: "memory");
            }
            __syncthreads();   // chunk c visible; all warps done with chunk c-1
            if (c + STAGES - 1 < NC) load_chunk(c + STAGES - 1);

            const uint32_t st = sbase + (uint32_t)(c % STAGES) * PLANES * PB;
#pragma unroll
            for (int kk = 0; kk < BK; kk += 16) {
                uint32_t af[2][4];
#pragma unroll
                for (int mi = 0; mi < 2; mi++) {
                    uint32_t addr = st +
                        (uint32_t)((rm + mi * 16 + (lane & 15)) * ROWB +
                                   (kk + (lane >> 4) * 8) * 2);
                    ldmx4(af[mi][0], af[mi][1], af[mi][2], af[mi][3], addr);
                }
                uint32_t bf[8][2];
#pragma unroll
                for (int nb = 0; nb < 4; nb++) {
                    int nrow = cn + nb * 16 + (lane & 7) + (((lane >> 4) & 1) << 3);
                    int kcol = kk + ((lane & 8) ? 8 : 0);
                    uint32_t addr = st + PB + (uint32_t)(nrow * ROWB + kcol * 2);
                    uint32_t r0, r1, r2, r3;
                    ldmx4(r0, r1, r2, r3, addr);
                    bf[nb * 2][0] = r0;      bf[nb * 2][1] = r1;
                    bf[nb * 2 + 1][0] = r2;  bf[nb * 2 + 1][1] = r3;
                }
#pragma unroll
                for (int mi = 0; mi < 2; mi++)
#pragma unroll
                    for (int ni = 0; ni < 8; ni++)
                        mma_fp16(acc[mi][ni], af[mi], bf[ni]);
            }
        }

        // ---------------- epilogue ----------------
        const int tg = lane >> 2;          // 0..7
        const int tc = (lane & 3) << 1;    // 0,2,4,6
#pragma unroll
        for (int mi = 0; mi < 2; mi++)
#pragma unroll
            for (int ni = 0; ni < 8; ni++)
#pragma unroll
                for (int rh = 0; rh < 2; rh++) {
                    int r  = rm + mi * 16 + tg + rh * 8;
                    int c0 = cn + ni * 8 + tc;
                    int gi = i0 + r;
                    if (gi < cnt) {
                        float v0 = acc[mi][ni][2 * rh];
                        float v1 = acc[mi][ni][2 * rh + 1];
                        if (isUp) {
                            float sw = row_w_s[r];
                            float f0 = sw * fmaxf(v0, 0.f); f0 *= f0;
                            float f1 = sw * fmaxf(v1, 0.f); f1 *= f1;
                            __half2 h2 = __floats2half2_rn(f0, f1);
                            *(__half2*)(g_h + ((size_t)e * T_TOK + gi) * HID + j0 + c0) = h2;
                        } else {
                            int t = row_tok_s[r] & 0xFFF;
                            // exactly 2 commutative fp32 adds per element -> deterministic
                            atomicAdd(outp + (size_t)t * DIM + j0 + c0, v0);
                            atomicAdd(outp + (size_t)t * DIM + j0 + c0 + 1, v1);
                        }
                    }
                }

        if (isUp) {
            __threadfence();      // each thread orders its h stores (release)
            __syncthreads();      // all threads' fences done
            if (tid == 0) atomicAdd(&g_done[e], 1);
        }
    }
}

// ---------------- launch -----------------------------------------------------
extern "C" void kernel_launch(void* const* d_in, const int* in_sizes, int n_in,
                              void* d_out, int out_size) {
    const float* x      = (const float*)d_in[0];
    const float* gate_w = (const float*)d_in[1];
    const float* w_up   = (const float*)d_in[2];
    const float* w_down = (const float*)d_in[3];
    const float* bias   = (const float*)d_in[4];
    float* out = (float*)d_out;

    constexpr int SMEM_GEMM = STAGES * PLANES * PB;   // 110592
    cudaFuncSetAttribute(moe_fused_gemm_kernel,
                         cudaFuncAttributeMaxDynamicSharedMemorySize, SMEM_GEMM);

    init_counts_kernel<<<1, 32>>>();
    cudaMemsetAsync(d_out, 0, (size_t)out_size * sizeof(float));

    {
        constexpr int NTOT = T_TOK * DIM + NEXP * HID * DIM + NEXP * DIM * HID;
        constexpr int CONV_BLOCKS = (NTOT / 8 + 255) / 256;
        fused_route_prepass_kernel<<<RB + CONV_BLOCKS, 256>>>(x, gate_w, bias,
                                                              w_up, w_down);
    }

    moe_fused_gemm_kernel<<<GRIDP, 256, SMEM_GEMM>>>(out);
    (void)in_sizes; (void)n_in;
}